// round 9
// baseline (speedup 1.0000x reference)
#include <cuda_runtime.h>
#include <cstdint>

// Problem constants
#define DIM_X 1024
#define H1    2048
#define H2    512
#define SL    8192
#define SU    16384
#define K_TRIES 8

// ---------------------------------------------------------------------------
// Device scratch (no allocations allowed)
// ---------------------------------------------------------------------------
__device__ float g_h[(size_t)SU * H1];        // 128 MB hidden buffer (reused l/u)
__device__ float g_feat_l[(size_t)SL * H2];   // 16 MB
__device__ int   g_a[SU];
__device__ int   g_b[SU];

// ---------------------------------------------------------------------------
// GEMM: C[M,N] = relu(A[M,K] @ B[K,N] + bias[N])
// BM=BN=128, BK=16, 256 threads, 8x8 microtile per thread.
// Double-buffered SMEM tiles: one __syncthreads per K-tile, LDGs for tile
// i+1 issued before the compute of tile i (latency hidden under FFMA issue).
// ---------------------------------------------------------------------------
#define BM 128
#define BN 128
#define BK 16

__global__ __launch_bounds__(256)
void gemm_bias_relu(const float* __restrict__ A, const float* __restrict__ B,
                    const float* __restrict__ bias, float* __restrict__ C,
                    int M, int N, int K) {
    __shared__ float As[2][BK][BM];
    __shared__ float Bs[2][BK][BN];

    const int tid = threadIdx.x;
    const int tx = tid & 15;      // 0..15  (N direction)
    const int ty = tid >> 4;      // 0..15  (M direction)

    const float* Aptr = A + (size_t)blockIdx.y * BM * K;
    const float* Bptr = B + (size_t)blockIdx.x * BN;

    // Per-thread load coordinates (fixed across tiles)
    const int a_row0 = tid >> 2;          // 0..63
    const int a_kc0  = tid & 3;
    const int a_row1 = (tid + 256) >> 2;  // 64..127
    const int a_kc1  = a_kc0;
    const int b_kr0  = tid >> 5;          // 0..7
    const int b_nc0  = tid & 31;
    const int b_kr1  = b_kr0 + 8;         // 8..15
    const int b_nc1  = b_nc0;

    float acc[8][8];
#pragma unroll
    for (int i = 0; i < 8; i++)
#pragma unroll
        for (int j = 0; j < 8; j++) acc[i][j] = 0.0f;

    // Prologue: load tile 0 into buffer 0
    {
        float4 va0 = *(const float4*)(Aptr + (size_t)a_row0 * K + a_kc0 * 4);
        float4 va1 = *(const float4*)(Aptr + (size_t)a_row1 * K + a_kc1 * 4);
        As[0][a_kc0 * 4 + 0][a_row0] = va0.x;
        As[0][a_kc0 * 4 + 1][a_row0] = va0.y;
        As[0][a_kc0 * 4 + 2][a_row0] = va0.z;
        As[0][a_kc0 * 4 + 3][a_row0] = va0.w;
        As[0][a_kc1 * 4 + 0][a_row1] = va1.x;
        As[0][a_kc1 * 4 + 1][a_row1] = va1.y;
        As[0][a_kc1 * 4 + 2][a_row1] = va1.z;
        As[0][a_kc1 * 4 + 3][a_row1] = va1.w;
        *(float4*)&Bs[0][b_kr0][b_nc0 * 4] =
            *(const float4*)(Bptr + (size_t)b_kr0 * N + b_nc0 * 4);
        *(float4*)&Bs[0][b_kr1][b_nc1 * 4] =
            *(const float4*)(Bptr + (size_t)b_kr1 * N + b_nc1 * 4);
    }
    __syncthreads();

    int buf = 0;
    for (int k0 = 0; k0 < K; k0 += BK) {
        const int nbuf = buf ^ 1;
        // Issue loads for the next tile first (into the idle buffer)
        if (k0 + BK < K) {
            const int kn = k0 + BK;
            float4 va0 = *(const float4*)(Aptr + (size_t)a_row0 * K + kn + a_kc0 * 4);
            float4 va1 = *(const float4*)(Aptr + (size_t)a_row1 * K + kn + a_kc1 * 4);
            float4 vb0 = *(const float4*)(Bptr + (size_t)(kn + b_kr0) * N + b_nc0 * 4);
            float4 vb1 = *(const float4*)(Bptr + (size_t)(kn + b_kr1) * N + b_nc1 * 4);
            As[nbuf][a_kc0 * 4 + 0][a_row0] = va0.x;
            As[nbuf][a_kc0 * 4 + 1][a_row0] = va0.y;
            As[nbuf][a_kc0 * 4 + 2][a_row0] = va0.z;
            As[nbuf][a_kc0 * 4 + 3][a_row0] = va0.w;
            As[nbuf][a_kc1 * 4 + 0][a_row1] = va1.x;
            As[nbuf][a_kc1 * 4 + 1][a_row1] = va1.y;
            As[nbuf][a_kc1 * 4 + 2][a_row1] = va1.z;
            As[nbuf][a_kc1 * 4 + 3][a_row1] = va1.w;
            *(float4*)&Bs[nbuf][b_kr0][b_nc0 * 4] = vb0;
            *(float4*)&Bs[nbuf][b_kr1][b_nc1 * 4] = vb1;
        }

        // Compute on current buffer
#pragma unroll
        for (int k = 0; k < BK; k++) {
            float ra[8], rb[8];
            *(float4*)&ra[0] = *(const float4*)&As[buf][k][ty * 8];
            *(float4*)&ra[4] = *(const float4*)&As[buf][k][ty * 8 + 4];
            *(float4*)&rb[0] = *(const float4*)&Bs[buf][k][tx * 8];
            *(float4*)&rb[4] = *(const float4*)&Bs[buf][k][tx * 8 + 4];
#pragma unroll
            for (int i = 0; i < 8; i++)
#pragma unroll
                for (int j = 0; j < 8; j++)
                    acc[i][j] += ra[i] * rb[j];
        }
        __syncthreads();
        buf = nbuf;
    }

    // Epilogue: bias + relu, vectorized stores
    const int row0 = blockIdx.y * BM + ty * 8;
    const int col0 = blockIdx.x * BN + tx * 8;
    float bcol[8];
#pragma unroll
    for (int j = 0; j < 8; j++) bcol[j] = bias[col0 + j];

#pragma unroll
    for (int i = 0; i < 8; i++) {
        float4 v0, v1;
        v0.x = fmaxf(acc[i][0] + bcol[0], 0.0f);
        v0.y = fmaxf(acc[i][1] + bcol[1], 0.0f);
        v0.z = fmaxf(acc[i][2] + bcol[2], 0.0f);
        v0.w = fmaxf(acc[i][3] + bcol[3], 0.0f);
        v1.x = fmaxf(acc[i][4] + bcol[4], 0.0f);
        v1.y = fmaxf(acc[i][5] + bcol[5], 0.0f);
        v1.z = fmaxf(acc[i][6] + bcol[6], 0.0f);
        v1.w = fmaxf(acc[i][7] + bcol[7], 0.0f);
        float* crow = C + (size_t)(row0 + i) * N + col0;
        *(float4*)(crow)     = v0;
        *(float4*)(crow + 4) = v1;
    }
}

// ---------------------------------------------------------------------------
// y_hat[r] = dot(feat_l[r,:], W3) + b3   (one warp per row)
// ---------------------------------------------------------------------------
__global__ void yhat_kernel(const float* __restrict__ feat_l,
                            const float* __restrict__ W3,
                            const float* __restrict__ b3,
                            float* __restrict__ out) {
    int warp = (blockIdx.x * blockDim.x + threadIdx.x) >> 5;
    int lane = threadIdx.x & 31;
    if (warp >= SL) return;
    const float* row = feat_l + (size_t)warp * H2;
    float s = 0.0f;
#pragma unroll
    for (int d = lane; d < H2; d += 32) s += row[d] * W3[d];
#pragma unroll
    for (int off = 16; off > 0; off >>= 1)
        s += __shfl_down_sync(0xFFFFFFFFu, s, off);
    if (lane == 0) out[warp] = s + b3[0];
}

// ---------------------------------------------------------------------------
// JAX threefry2x32 (20 rounds), exact replication
// ---------------------------------------------------------------------------
__device__ __forceinline__ uint32_t rotl32(uint32_t v, int d) {
    return (v << d) | (v >> (32 - d));
}

__device__ __forceinline__ void threefry2x32(uint32_t k0, uint32_t k1,
                                             uint32_t x0, uint32_t x1,
                                             uint32_t& o0, uint32_t& o1) {
    uint32_t k2 = k0 ^ k1 ^ 0x1BD11BDAu;
    x0 += k0; x1 += k1;
#define TF_RND(r) { x0 += x1; x1 = rotl32(x1, r); x1 ^= x0; }
    TF_RND(13) TF_RND(15) TF_RND(26) TF_RND(6)
    x0 += k1; x1 += k2 + 1u;
    TF_RND(17) TF_RND(29) TF_RND(16) TF_RND(24)
    x0 += k2; x1 += k0 + 2u;
    TF_RND(13) TF_RND(15) TF_RND(26) TF_RND(6)
    x0 += k0; x1 += k1 + 3u;
    TF_RND(17) TF_RND(29) TF_RND(16) TF_RND(24)
    x0 += k1; x1 += k2 + 4u;
    TF_RND(13) TF_RND(15) TF_RND(26) TF_RND(6)
    x0 += k2; x1 += k0 + 5u;
#undef TF_RND
    o0 = x0; o1 = x1;
}

// ---------------------------------------------------------------------------
// Pair sampling — JAX *partitionable* threefry path (default since JAX 0.4.26):
//
//   split(key, n): key_j = (o0, o1) of TF(key, (0, j))          [fold-like]
//   random_bits(key, 32, shape): elem at flat index i =
//        o0 ^ o1  of TF(key, (0, i))                            [xor of block]
//   randint(key, shape, 0, span) for power-of-2 span:
//        k1, k2 = split(key); multiplier = ((2^16)%span)^2 % span = 0
//        -> result = random_bits(k2, 32, shape) & (span-1)      [only k2 used]
//
// Chain:  ka = TF((0,42),(0,0)), kb = TF((0,42),(0,1))
//         ka2 = TF(ka,(0,1)),    kb2 = TF(kb,(0,1))
//         ia(s,k) = xorbits(ka2, s*8+k) & 8191 ; ib likewise with kb2
// ---------------------------------------------------------------------------
__global__ void sample_pairs_kernel(const float* __restrict__ y_l,
                                    int* __restrict__ a_out,
                                    int* __restrict__ b_out) {
    int s = blockIdx.x * blockDim.x + threadIdx.x;
    if (s >= SU) return;

    uint32_t o0, o1;
    // partitionable split of key(42) = (0,42)
    uint32_t ka0, ka1, kb0, kb1;
    threefry2x32(0u, 42u, 0u, 0u, ka0, ka1);   // ka = split(...)[0]
    threefry2x32(0u, 42u, 0u, 1u, kb0, kb1);   // kb = split(...)[1]

    // randint's internal split: lower key k2 = split(key)[1] = TF(key,(0,1))
    uint32_t ka2_0, ka2_1, kb2_0, kb2_1;
    threefry2x32(ka0, ka1, 0u, 1u, ka2_0, ka2_1);
    threefry2x32(kb0, kb1, 0u, 1u, kb2_0, kb2_1);

    int a = -1, b = -1, a_first = 0, b_first = 0;
#pragma unroll
    for (int k = 0; k < K_TRIES; k++) {
        uint32_t i = (uint32_t)s * K_TRIES + k;
        threefry2x32(ka2_0, ka2_1, 0u, i, o0, o1);
        int ia = (int)((o0 ^ o1) & (SL - 1));
        threefry2x32(kb2_0, kb2_1, 0u, i, o0, o1);
        int ib = (int)((o0 ^ o1) & (SL - 1));
        if (k == 0) { a_first = ia; b_first = ib; }
        if (a < 0 && ia != ib && y_l[ia] != y_l[ib]) { a = ia; b = ib; }
    }
    if (a < 0) { a = a_first; b = b_first; }  // argmax over all-False -> index 0
    a_out[s] = a;
    b_out[s] = b;
}

// ---------------------------------------------------------------------------
// feat_comb[s] = k * feat_l[a] + (1-k) * feat_l[b],  k = (y_u[s]-y_l[b])/(y_l[a]-y_l[b])
// one block per sample, 128 threads x float4
// ---------------------------------------------------------------------------
__global__ void combine_kernel(const float* __restrict__ feat_l,
                               const float* __restrict__ y_l,
                               const float* __restrict__ y_u,
                               const int* __restrict__ a_idx,
                               const int* __restrict__ b_idx,
                               float* __restrict__ out) {
    int s = blockIdx.x;
    int a = a_idx[s], b = b_idx[s];
    float ya = y_l[a], yb = y_l[b];
    float kc = (y_u[s] - yb) / (ya - yb);
    float km = 1.0f - kc;
    const float4* fa = (const float4*)(feat_l + (size_t)a * H2);
    const float4* fb = (const float4*)(feat_l + (size_t)b * H2);
    float4* o = (float4*)(out + (size_t)s * H2);
    for (int d = threadIdx.x; d < H2 / 4; d += blockDim.x) {
        float4 va = fa[d], vb = fb[d], r;
        r.x = kc * va.x + km * vb.x;
        r.y = kc * va.y + km * vb.y;
        r.z = kc * va.z + km * vb.z;
        r.w = kc * va.w + km * vb.w;
        o[d] = r;
    }
}

// ---------------------------------------------------------------------------
// Launch
// ---------------------------------------------------------------------------
extern "C" void kernel_launch(void* const* d_in, const int* in_sizes, int n_in,
                              void* d_out, int out_size) {
    const float* X_l = (const float*)d_in[0];
    const float* y_l = (const float*)d_in[1];
    const float* X_u = (const float*)d_in[2];
    const float* y_u = (const float*)d_in[3];
    const float* W1  = (const float*)d_in[4];
    const float* b1  = (const float*)d_in[5];
    const float* W2  = (const float*)d_in[6];
    const float* b2  = (const float*)d_in[7];
    const float* W3  = (const float*)d_in[8];
    const float* b3  = (const float*)d_in[9];

    float* out = (float*)d_out;
    float* out_feat_u    = out;                              // [SU, H2]
    float* out_feat_comb = out + (size_t)SU * H2;            // [SU, H2]
    float* out_yhat      = out + (size_t)2 * SU * H2;        // [SL, 1]

    float *ph, *pfl;
    int *pa, *pb;
    cudaGetSymbolAddress((void**)&ph,  g_h);
    cudaGetSymbolAddress((void**)&pfl, g_feat_l);
    cudaGetSymbolAddress((void**)&pa,  g_a);
    cudaGetSymbolAddress((void**)&pb,  g_b);

    // --- unlabeled branch: feat_u -> d_out segment 0
    gemm_bias_relu<<<dim3(H1 / BN, SU / BM), 256>>>(X_u, W1, b1, ph, SU, H1, DIM_X);
    gemm_bias_relu<<<dim3(H2 / BN, SU / BM), 256>>>(ph, W2, b2, out_feat_u, SU, H2, H1);

    // --- labeled branch: feat_l -> scratch (reuse g_h)
    gemm_bias_relu<<<dim3(H1 / BN, SL / BM), 256>>>(X_l, W1, b1, ph, SL, H1, DIM_X);
    gemm_bias_relu<<<dim3(H2 / BN, SL / BM), 256>>>(ph, W2, b2, pfl, SL, H2, H1);

    // --- y_hat
    yhat_kernel<<<SL / 8, 256>>>(pfl, W3, b3, out_yhat);

    // --- pair sampling (exact JAX partitionable-threefry replication) + combine
    sample_pairs_kernel<<<SU / 256, 256>>>(y_l, pa, pb);
    combine_kernel<<<SU, 128>>>(pfl, y_l, y_u, pa, pb, out_feat_comb);
}

// round 11
// speedup vs baseline: 1.5225x; 1.5225x over previous
#include <cuda_runtime.h>
#include <cuda_bf16.h>
#include <cstdint>

// Problem constants
#define DIM_X 1024
#define H1    2048
#define H2    512
#define SL    8192
#define SU    16384
#define K_TRIES 8

// ---------------------------------------------------------------------------
// Device scratch (no allocations allowed)
// ---------------------------------------------------------------------------
__device__ float g_h[(size_t)SU * H1];        // 128 MB hidden buffer (reused l/u)
__device__ float g_feat_l[(size_t)SL * H2];   // 16 MB
__device__ int   g_a[SU];
__device__ int   g_b[SU];

// ===========================================================================
// Tensor-core GEMM: C[M,N] = relu(A[M,K] @ B[K,N] + bias[N])
// bf16x3 split (hi+lo; hi*hi + hi*lo + lo*hi), fp32 accumulate -> ~1e-5 rel.
// BM=128, BN=64, BK=64. 8 warps, warp tile 32x32 (2 m16 x 4 n8 mma tiles).
// SMEM: 128B rows, 16B-chunk XOR swizzle; ldmatrix (A) / ldmatrix.trans (B).
// Double-buffered (96KB dynamic), one __syncthreads per K-tile.
// M%128==0, N%64==0, K%64==0 hold for all four GEMMs here.
// ===========================================================================
#define BM 128
#define BN 64
#define BK 64
// stage layout: Ahi[128][64]bf16 16KB | Alo 16KB | Bhi[64][64] 8KB | Blo 8KB
#define ST_ALO 16384
#define ST_BHI 32768
#define ST_BLO 40960
#define ST_SZ  49152

__device__ __forceinline__ uint32_t pk_bf16(__nv_bfloat16 a, __nv_bfloat16 b) {
    return (uint32_t)__bfloat16_as_ushort(a) | ((uint32_t)__bfloat16_as_ushort(b) << 16);
}

__device__ __forceinline__ void ldsm4(uint32_t* r, uint32_t addr) {
    asm volatile("ldmatrix.sync.aligned.m8n8.x4.shared.b16 {%0,%1,%2,%3}, [%4];"
                 : "=r"(r[0]), "=r"(r[1]), "=r"(r[2]), "=r"(r[3]) : "r"(addr));
}
__device__ __forceinline__ void ldsm4t(uint32_t* r, uint32_t addr) {
    asm volatile("ldmatrix.sync.aligned.m8n8.x4.trans.shared.b16 {%0,%1,%2,%3}, [%4];"
                 : "=r"(r[0]), "=r"(r[1]), "=r"(r[2]), "=r"(r[3]) : "r"(addr));
}
__device__ __forceinline__ void mma16816(float* c, const uint32_t* a, const uint32_t* b) {
    asm volatile("mma.sync.aligned.m16n8k16.row.col.f32.bf16.bf16.f32 "
                 "{%0,%1,%2,%3}, {%4,%5,%6,%7}, {%8,%9}, {%0,%1,%2,%3};"
                 : "+f"(c[0]), "+f"(c[1]), "+f"(c[2]), "+f"(c[3])
                 : "r"(a[0]), "r"(a[1]), "r"(a[2]), "r"(a[3]), "r"(b[0]), "r"(b[1]));
}

__global__ __launch_bounds__(256, 2)
void gemm_mma_bias_relu(const float* __restrict__ A, const float* __restrict__ B,
                        const float* __restrict__ bias, float* __restrict__ C,
                        int M, int N, int K) {
    extern __shared__ char sm[];
    const int tid  = threadIdx.x;
    const int lane = tid & 31;
    const int wid  = tid >> 5;
    const int wm   = (wid >> 1) * 32;   // warp M offset in CTA tile
    const int wn   = (wid & 1) * 32;    // warp N offset
    const int bm   = blockIdx.y * BM;
    const int bn   = blockIdx.x * BN;

    const uint32_t smBase = (uint32_t)__cvta_generic_to_shared(sm);

    float acc[2][4][4];
#pragma unroll
    for (int i = 0; i < 2; i++)
#pragma unroll
        for (int j = 0; j < 4; j++)
#pragma unroll
            for (int v = 0; v < 4; v++) acc[i][j][v] = 0.0f;

    // Loader coordinates
    const int a_r0 = tid >> 4;     // 0..15
    const int a_kv = tid & 15;     // float4 index along K
    const int b_k0 = tid >> 4;     // 0..15
    const int b_n4 = tid & 15;     // float4 index along N

    auto load_tile = [&](int kt, int stg) {
        char* base = sm + stg * ST_SZ;
        const float* Ag = A + (size_t)bm * K + kt * BK;
#pragma unroll
        for (int p = 0; p < 8; ++p) {
            const int r = a_r0 + p * 16;
            float4 f = *(const float4*)(Ag + (size_t)r * K + a_kv * 4);
            __nv_bfloat16 h0 = __float2bfloat16(f.x), h1 = __float2bfloat16(f.y);
            __nv_bfloat16 h2 = __float2bfloat16(f.z), h3 = __float2bfloat16(f.w);
            __nv_bfloat16 l0 = __float2bfloat16(f.x - __bfloat162float(h0));
            __nv_bfloat16 l1 = __float2bfloat16(f.y - __bfloat162float(h1));
            __nv_bfloat16 l2 = __float2bfloat16(f.z - __bfloat162float(h2));
            __nv_bfloat16 l3 = __float2bfloat16(f.w - __bfloat162float(h3));
            const int off = r * 128 + ((((a_kv >> 1) ^ (r & 7)) & 7) << 4) + (a_kv & 1) * 8;
            *(uint2*)(base + off)          = make_uint2(pk_bf16(h0, h1), pk_bf16(h2, h3));
            *(uint2*)(base + ST_ALO + off) = make_uint2(pk_bf16(l0, l1), pk_bf16(l2, l3));
        }
        const float* Bg = B + (size_t)(kt * BK) * N + bn;
#pragma unroll
        for (int p = 0; p < 4; ++p) {
            const int k = b_k0 + p * 16;
            float4 f = *(const float4*)(Bg + (size_t)k * N + b_n4 * 4);
            __nv_bfloat16 h0 = __float2bfloat16(f.x), h1 = __float2bfloat16(f.y);
            __nv_bfloat16 h2 = __float2bfloat16(f.z), h3 = __float2bfloat16(f.w);
            __nv_bfloat16 l0 = __float2bfloat16(f.x - __bfloat162float(h0));
            __nv_bfloat16 l1 = __float2bfloat16(f.y - __bfloat162float(h1));
            __nv_bfloat16 l2 = __float2bfloat16(f.z - __bfloat162float(h2));
            __nv_bfloat16 l3 = __float2bfloat16(f.w - __bfloat162float(h3));
            const int off = k * 128 + ((((b_n4 >> 1) ^ (k & 7)) & 7) << 4) + (b_n4 & 1) * 8;
            *(uint2*)(base + ST_BHI + off) = make_uint2(pk_bf16(h0, h1), pk_bf16(h2, h3));
            *(uint2*)(base + ST_BLO + off) = make_uint2(pk_bf16(l0, l1), pk_bf16(l2, l3));
        }
    };

    const int NT = K / BK;
    load_tile(0, 0);
    __syncthreads();

    int stg = 0;
    for (int t = 0; t < NT; ++t) {
        if (t + 1 < NT) load_tile(t + 1, stg ^ 1);

        const uint32_t sb = smBase + stg * ST_SZ;
#pragma unroll
        for (int ks = 0; ks < 4; ++ks) {
            const int k16 = ks * 16;
            uint32_t ah[2][4], al[2][4], bh[2][4], bl[2][4];
#pragma unroll
            for (int mt = 0; mt < 2; ++mt) {
                const int r  = wm + mt * 16 + (lane & 15);
                const int kc = k16 + (lane >> 4) * 8;
                const uint32_t ad = sb + r * 128 + ((((kc >> 3) ^ (r & 7)) & 7) << 4);
                ldsm4(ah[mt], ad);
                ldsm4(al[mt], ad + ST_ALO);
            }
#pragma unroll
            for (int j = 0; j < 2; ++j) {
                const int kl = k16 + (lane & 15);
                const int nl = wn + j * 16 + (lane >> 4) * 8;
                const uint32_t bd = sb + ST_BHI + kl * 128 + ((((nl >> 3) ^ (kl & 7)) & 7) << 4);
                ldsm4t(bh[j], bd);
                ldsm4t(bl[j], bd + (ST_BLO - ST_BHI));
            }
#pragma unroll
            for (int mt = 0; mt < 2; ++mt)
#pragma unroll
                for (int nt = 0; nt < 4; ++nt) {
                    const int j = nt >> 1, s = (nt & 1) * 2;
                    mma16816(acc[mt][nt], ah[mt], &bh[j][s]);   // hi*hi
                    mma16816(acc[mt][nt], ah[mt], &bl[j][s]);   // hi*lo
                    mma16816(acc[mt][nt], al[mt], &bh[j][s]);   // lo*hi
                }
        }
        __syncthreads();
        stg ^= 1;
    }

    // Epilogue: bias + relu
#pragma unroll
    for (int nt = 0; nt < 4; ++nt) {
        const int cn = bn + wn + nt * 8 + (lane & 3) * 2;
        const float2 bv = *(const float2*)(bias + cn);
#pragma unroll
        for (int mt = 0; mt < 2; ++mt) {
            const int r = bm + wm + mt * 16 + (lane >> 2);
            float2 v0, v1;
            v0.x = fmaxf(acc[mt][nt][0] + bv.x, 0.0f);
            v0.y = fmaxf(acc[mt][nt][1] + bv.y, 0.0f);
            v1.x = fmaxf(acc[mt][nt][2] + bv.x, 0.0f);
            v1.y = fmaxf(acc[mt][nt][3] + bv.y, 0.0f);
            *(float2*)(C + (size_t)r * N + cn)       = v0;
            *(float2*)(C + (size_t)(r + 8) * N + cn) = v1;
        }
    }
}

// ---------------------------------------------------------------------------
// y_hat[r] = dot(feat_l[r,:], W3) + b3   (one warp per row)
// ---------------------------------------------------------------------------
__global__ void yhat_kernel(const float* __restrict__ feat_l,
                            const float* __restrict__ W3,
                            const float* __restrict__ b3,
                            float* __restrict__ out) {
    int warp = (blockIdx.x * blockDim.x + threadIdx.x) >> 5;
    int lane = threadIdx.x & 31;
    if (warp >= SL) return;
    const float* row = feat_l + (size_t)warp * H2;
    float s = 0.0f;
#pragma unroll
    for (int d = lane; d < H2; d += 32) s += row[d] * W3[d];
#pragma unroll
    for (int off = 16; off > 0; off >>= 1)
        s += __shfl_down_sync(0xFFFFFFFFu, s, off);
    if (lane == 0) out[warp] = s + b3[0];
}

// ---------------------------------------------------------------------------
// JAX threefry2x32 (20 rounds), exact replication
// ---------------------------------------------------------------------------
__device__ __forceinline__ uint32_t rotl32(uint32_t v, int d) {
    return (v << d) | (v >> (32 - d));
}

__device__ __forceinline__ void threefry2x32(uint32_t k0, uint32_t k1,
                                             uint32_t x0, uint32_t x1,
                                             uint32_t& o0, uint32_t& o1) {
    uint32_t k2 = k0 ^ k1 ^ 0x1BD11BDAu;
    x0 += k0; x1 += k1;
#define TF_RND(r) { x0 += x1; x1 = rotl32(x1, r); x1 ^= x0; }
    TF_RND(13) TF_RND(15) TF_RND(26) TF_RND(6)
    x0 += k1; x1 += k2 + 1u;
    TF_RND(17) TF_RND(29) TF_RND(16) TF_RND(24)
    x0 += k2; x1 += k0 + 2u;
    TF_RND(13) TF_RND(15) TF_RND(26) TF_RND(6)
    x0 += k0; x1 += k1 + 3u;
    TF_RND(17) TF_RND(29) TF_RND(16) TF_RND(24)
    x0 += k1; x1 += k2 + 4u;
    TF_RND(13) TF_RND(15) TF_RND(26) TF_RND(6)
    x0 += k2; x1 += k0 + 5u;
#undef TF_RND
    o0 = x0; o1 = x1;
}

// ---------------------------------------------------------------------------
// Pair sampling — JAX *partitionable* threefry path (default since JAX 0.4.26):
//   split(key, n): key_j = TF(key, (0, j))                      [fold-like]
//   random_bits(key, 32, shape)[i] = o0 ^ o1 of TF(key, (0, i)) [xor of block]
//   randint(key, shape, 0, 2^p): k1,k2 = split(key); multiplier = 0
//        -> result = random_bits(k2, 32, shape) & (2^p - 1)     [only k2 used]
// ---------------------------------------------------------------------------
__global__ void sample_pairs_kernel(const float* __restrict__ y_l,
                                    int* __restrict__ a_out,
                                    int* __restrict__ b_out) {
    int s = blockIdx.x * blockDim.x + threadIdx.x;
    if (s >= SU) return;

    uint32_t o0, o1;
    uint32_t ka0, ka1, kb0, kb1;
    threefry2x32(0u, 42u, 0u, 0u, ka0, ka1);   // ka = split(key(42))[0]
    threefry2x32(0u, 42u, 0u, 1u, kb0, kb1);   // kb = split(key(42))[1]

    uint32_t ka2_0, ka2_1, kb2_0, kb2_1;
    threefry2x32(ka0, ka1, 0u, 1u, ka2_0, ka2_1);  // randint inner lower key
    threefry2x32(kb0, kb1, 0u, 1u, kb2_0, kb2_1);

    int a = -1, b = -1, a_first = 0, b_first = 0;
#pragma unroll
    for (int k = 0; k < K_TRIES; k++) {
        uint32_t i = (uint32_t)s * K_TRIES + k;
        threefry2x32(ka2_0, ka2_1, 0u, i, o0, o1);
        int ia = (int)((o0 ^ o1) & (SL - 1));
        threefry2x32(kb2_0, kb2_1, 0u, i, o0, o1);
        int ib = (int)((o0 ^ o1) & (SL - 1));
        if (k == 0) { a_first = ia; b_first = ib; }
        if (a < 0 && ia != ib && y_l[ia] != y_l[ib]) { a = ia; b = ib; }
    }
    if (a < 0) { a = a_first; b = b_first; }  // argmax over all-False -> index 0
    a_out[s] = a;
    b_out[s] = b;
}

// ---------------------------------------------------------------------------
// feat_comb[s] = k * feat_l[a] + (1-k) * feat_l[b]
// ---------------------------------------------------------------------------
__global__ void combine_kernel(const float* __restrict__ feat_l,
                               const float* __restrict__ y_l,
                               const float* __restrict__ y_u,
                               const int* __restrict__ a_idx,
                               const int* __restrict__ b_idx,
                               float* __restrict__ out) {
    int s = blockIdx.x;
    int a = a_idx[s], b = b_idx[s];
    float ya = y_l[a], yb = y_l[b];
    float kc = (y_u[s] - yb) / (ya - yb);
    float km = 1.0f - kc;
    const float4* fa = (const float4*)(feat_l + (size_t)a * H2);
    const float4* fb = (const float4*)(feat_l + (size_t)b * H2);
    float4* o = (float4*)(out + (size_t)s * H2);
    for (int d = threadIdx.x; d < H2 / 4; d += blockDim.x) {
        float4 va = fa[d], vb = fb[d], r;
        r.x = kc * va.x + km * vb.x;
        r.y = kc * va.y + km * vb.y;
        r.z = kc * va.z + km * vb.z;
        r.w = kc * va.w + km * vb.w;
        o[d] = r;
    }
}

// ---------------------------------------------------------------------------
// Launch
// ---------------------------------------------------------------------------
extern "C" void kernel_launch(void* const* d_in, const int* in_sizes, int n_in,
                              void* d_out, int out_size) {
    const float* X_l = (const float*)d_in[0];
    const float* y_l = (const float*)d_in[1];
    const float* X_u = (const float*)d_in[2];
    const float* y_u = (const float*)d_in[3];
    const float* W1  = (const float*)d_in[4];
    const float* b1  = (const float*)d_in[5];
    const float* W2  = (const float*)d_in[6];
    const float* b2  = (const float*)d_in[7];
    const float* W3  = (const float*)d_in[8];
    const float* b3  = (const float*)d_in[9];

    float* out = (float*)d_out;
    float* out_feat_u    = out;                              // [SU, H2]
    float* out_feat_comb = out + (size_t)SU * H2;            // [SU, H2]
    float* out_yhat      = out + (size_t)2 * SU * H2;        // [SL, 1]

    float *ph, *pfl;
    int *pa, *pb;
    cudaGetSymbolAddress((void**)&ph,  g_h);
    cudaGetSymbolAddress((void**)&pfl, g_feat_l);
    cudaGetSymbolAddress((void**)&pa,  g_a);
    cudaGetSymbolAddress((void**)&pb,  g_b);

    cudaFuncSetAttribute(gemm_mma_bias_relu,
                         cudaFuncAttributeMaxDynamicSharedMemorySize, 2 * ST_SZ);

    // --- unlabeled branch: feat_u -> d_out segment 0
    gemm_mma_bias_relu<<<dim3(H1 / BN, SU / BM), 256, 2 * ST_SZ>>>(X_u, W1, b1, ph, SU, H1, DIM_X);
    gemm_mma_bias_relu<<<dim3(H2 / BN, SU / BM), 256, 2 * ST_SZ>>>(ph, W2, b2, out_feat_u, SU, H2, H1);

    // --- labeled branch: feat_l -> scratch
    gemm_mma_bias_relu<<<dim3(H1 / BN, SL / BM), 256, 2 * ST_SZ>>>(X_l, W1, b1, ph, SL, H1, DIM_X);
    gemm_mma_bias_relu<<<dim3(H2 / BN, SL / BM), 256, 2 * ST_SZ>>>(ph, W2, b2, pfl, SL, H2, H1);

    // --- y_hat
    yhat_kernel<<<SL / 8, 256>>>(pfl, W3, b3, out_yhat);

    // --- pair sampling (exact JAX partitionable-threefry replication) + combine
    sample_pairs_kernel<<<SU / 256, 256>>>(y_l, pa, pb);
    combine_kernel<<<SU, 128>>>(pfl, y_l, y_u, pa, pb, out_feat_comb);
}

// round 13
// speedup vs baseline: 3.2344x; 2.1245x over previous
#include <cuda_runtime.h>
#include <cuda_bf16.h>
#include <cstdint>

// Problem constants
#define DIM_X 1024
#define H1    2048
#define H2    512
#define SL    8192
#define SU    16384
#define K_TRIES 8

// ---------------------------------------------------------------------------
// Device scratch (no allocations allowed). 16B-aligned for cp.async.
// ---------------------------------------------------------------------------
__device__ __align__(16) __nv_bfloat16 g_Xu_hi[(size_t)SU * DIM_X];
__device__ __align__(16) __nv_bfloat16 g_Xu_lo[(size_t)SU * DIM_X];
__device__ __align__(16) __nv_bfloat16 g_Xl_hi[(size_t)SL * DIM_X];
__device__ __align__(16) __nv_bfloat16 g_Xl_lo[(size_t)SL * DIM_X];
__device__ __align__(16) __nv_bfloat16 g_W1_hi[(size_t)DIM_X * H1];
__device__ __align__(16) __nv_bfloat16 g_W1_lo[(size_t)DIM_X * H1];
__device__ __align__(16) __nv_bfloat16 g_W2_hi[(size_t)H1 * H2];
__device__ __align__(16) __nv_bfloat16 g_W2_lo[(size_t)H1 * H2];
__device__ __align__(16) __nv_bfloat16 g_h_hi[(size_t)SU * H1];   // hidden, reused l/u
__device__ __align__(16) __nv_bfloat16 g_h_lo[(size_t)SU * H1];
__device__ __align__(16) float g_feat_l[(size_t)SL * H2];
__device__ int g_a[SU];
__device__ int g_b[SU];

// ---------------------------------------------------------------------------
// helpers
// ---------------------------------------------------------------------------
__device__ __forceinline__ uint32_t pk_bf16(__nv_bfloat16 a, __nv_bfloat16 b) {
    return (uint32_t)__bfloat16_as_ushort(a) | ((uint32_t)__bfloat16_as_ushort(b) << 16);
}

// fp32 -> (hi, lo) bf16 split, vectorized x4
__global__ void cvt_hilo(const float4* __restrict__ in, uint2* __restrict__ hi,
                         uint2* __restrict__ lo, int n4) {
    int i = blockIdx.x * blockDim.x + threadIdx.x;
    if (i >= n4) return;
    float4 f = in[i];
    __nv_bfloat16 h0 = __float2bfloat16(f.x), h1 = __float2bfloat16(f.y);
    __nv_bfloat16 h2 = __float2bfloat16(f.z), h3 = __float2bfloat16(f.w);
    __nv_bfloat16 l0 = __float2bfloat16(f.x - __bfloat162float(h0));
    __nv_bfloat16 l1 = __float2bfloat16(f.y - __bfloat162float(h1));
    __nv_bfloat16 l2 = __float2bfloat16(f.z - __bfloat162float(h2));
    __nv_bfloat16 l3 = __float2bfloat16(f.w - __bfloat162float(h3));
    hi[i] = make_uint2(pk_bf16(h0, h1), pk_bf16(h2, h3));
    lo[i] = make_uint2(pk_bf16(l0, l1), pk_bf16(l2, l3));
}

__device__ __forceinline__ void ldsm4(uint32_t* r, uint32_t addr) {
    asm volatile("ldmatrix.sync.aligned.m8n8.x4.shared.b16 {%0,%1,%2,%3}, [%4];"
                 : "=r"(r[0]), "=r"(r[1]), "=r"(r[2]), "=r"(r[3]) : "r"(addr));
}
__device__ __forceinline__ void ldsm4t(uint32_t* r, uint32_t addr) {
    asm volatile("ldmatrix.sync.aligned.m8n8.x4.trans.shared.b16 {%0,%1,%2,%3}, [%4];"
                 : "=r"(r[0]), "=r"(r[1]), "=r"(r[2]), "=r"(r[3]) : "r"(addr));
}
__device__ __forceinline__ void mma16816(float* c, const uint32_t* a, const uint32_t* b) {
    asm volatile("mma.sync.aligned.m16n8k16.row.col.f32.bf16.bf16.f32 "
                 "{%0,%1,%2,%3}, {%4,%5,%6,%7}, {%8,%9}, {%0,%1,%2,%3};"
                 : "+f"(c[0]), "+f"(c[1]), "+f"(c[2]), "+f"(c[3])
                 : "r"(a[0]), "r"(a[1]), "r"(a[2]), "r"(a[3]), "r"(b[0]), "r"(b[1]));
}
#define CP16(so, gp) \
    asm volatile("cp.async.cg.shared.global [%0], [%1], 16;\n" :: "r"(so), "l"(gp))
#define CP_COMMIT()  asm volatile("cp.async.commit_group;\n" ::: "memory")
#define CP_WAIT0()   asm volatile("cp.async.wait_group 0;\n" ::: "memory")

// ===========================================================================
// Tensor-core GEMM on pre-split bf16 operands:
//   C = relu(A @ B + bias);  C written as fp32 (Cf) and/or bf16 hi/lo (Chi/Clo)
// bf16x3: hi*hi + hi*lo + lo*hi, fp32 accumulate.
// BM=128, BN=64, BK=64; 8 warps, warp tile 32x32; cp.async double buffer.
// ===========================================================================
#define BM 128
#define BN 64
#define BK 64
#define ST_ALO 16384
#define ST_BHI 32768
#define ST_BLO 40960
#define ST_SZ  49152

__global__ __launch_bounds__(256, 2)
void gemm_bf16x3(const __nv_bfloat16* __restrict__ Ahi, const __nv_bfloat16* __restrict__ Alo,
                 const __nv_bfloat16* __restrict__ Bhi, const __nv_bfloat16* __restrict__ Blo,
                 const float* __restrict__ bias,
                 float* __restrict__ Cf,
                 __nv_bfloat16* __restrict__ Chi, __nv_bfloat16* __restrict__ Clo,
                 int M, int N, int K) {
    extern __shared__ char sm[];
    const int tid  = threadIdx.x;
    const int lane = tid & 31;
    const int wid  = tid >> 5;
    const int wm   = (wid >> 1) * 32;
    const int wn   = (wid & 1) * 32;
    const int bm   = blockIdx.y * BM;
    const int bn   = blockIdx.x * BN;

    const uint32_t smBase = (uint32_t)__cvta_generic_to_shared(sm);

    float acc[2][4][4];
#pragma unroll
    for (int i = 0; i < 2; i++)
#pragma unroll
        for (int j = 0; j < 4; j++)
#pragma unroll
            for (int v = 0; v < 4; v++) acc[i][j][v] = 0.0f;

    auto load_stage = [&](int kt, int stg) {
        const uint32_t base = smBase + stg * ST_SZ;
        const size_t a0 = (size_t)bm * K + (size_t)kt * BK;
        const size_t b0 = (size_t)kt * BK * N + bn;
#pragma unroll
        for (int p = 0; p < 4; ++p) {              // A: 128 rows x 8 chunks (x2 for hi/lo)
            const int c = tid + p * 256;
            const int r = c >> 3, ch = c & 7;
            const uint32_t so = base + r * 128 + (((ch ^ (r & 7)) & 7) << 4);
            const size_t g = a0 + (size_t)r * K + ch * 8;
            CP16(so, Ahi + g);
            CP16(so + ST_ALO, Alo + g);
        }
#pragma unroll
        for (int p = 0; p < 2; ++p) {              // B: 64 rows x 8 chunks (x2)
            const int c = tid + p * 256;
            const int k = c >> 3, ch = c & 7;
            const uint32_t so = base + ST_BHI + k * 128 + (((ch ^ (k & 7)) & 7) << 4);
            const size_t g = b0 + (size_t)k * N + ch * 8;
            CP16(so, Bhi + g);
            CP16(so + (ST_BLO - ST_BHI), Blo + g);
        }
        CP_COMMIT();
    };

    const int NT = K / BK;
    load_stage(0, 0);

    int stg = 0;
    for (int t = 0; t < NT; ++t) {
        CP_WAIT0();
        __syncthreads();
        if (t + 1 < NT) load_stage(t + 1, stg ^ 1);

        const uint32_t sb = smBase + stg * ST_SZ;
#pragma unroll
        for (int ks = 0; ks < 4; ++ks) {
            const int k16 = ks * 16;
            uint32_t ah[2][4], al[2][4], bh[2][4], bl[2][4];
#pragma unroll
            for (int mt = 0; mt < 2; ++mt) {
                const int r  = wm + mt * 16 + (lane & 15);
                const int kc = k16 + (lane >> 4) * 8;
                const uint32_t ad = sb + r * 128 + ((((kc >> 3) ^ (r & 7)) & 7) << 4);
                ldsm4(ah[mt], ad);
                ldsm4(al[mt], ad + ST_ALO);
            }
#pragma unroll
            for (int j = 0; j < 2; ++j) {
                const int kl = k16 + (lane & 15);
                const int nl = wn + j * 16 + (lane >> 4) * 8;
                const uint32_t bd = sb + ST_BHI + kl * 128 + ((((nl >> 3) ^ (kl & 7)) & 7) << 4);
                ldsm4t(bh[j], bd);
                ldsm4t(bl[j], bd + (ST_BLO - ST_BHI));
            }
#pragma unroll
            for (int mt = 0; mt < 2; ++mt)
#pragma unroll
                for (int nt = 0; nt < 4; ++nt) {
                    const int j = nt >> 1, s = (nt & 1) * 2;
                    mma16816(acc[mt][nt], ah[mt], &bh[j][s]);   // hi*hi
                    mma16816(acc[mt][nt], ah[mt], &bl[j][s]);   // hi*lo
                    mma16816(acc[mt][nt], al[mt], &bh[j][s]);   // lo*hi
                }
        }
        __syncthreads();
        stg ^= 1;
    }

    // Epilogue: bias + relu; fp32 and/or bf16 hi/lo stores
#pragma unroll
    for (int nt = 0; nt < 4; ++nt) {
        const int cn = bn + wn + nt * 8 + (lane & 3) * 2;
        const float2 bv = *(const float2*)(bias + cn);
#pragma unroll
        for (int mt = 0; mt < 2; ++mt) {
            const int r0 = bm + wm + mt * 16 + (lane >> 2);
            float v[2][2];
            v[0][0] = fmaxf(acc[mt][nt][0] + bv.x, 0.0f);
            v[0][1] = fmaxf(acc[mt][nt][1] + bv.y, 0.0f);
            v[1][0] = fmaxf(acc[mt][nt][2] + bv.x, 0.0f);
            v[1][1] = fmaxf(acc[mt][nt][3] + bv.y, 0.0f);
#pragma unroll
            for (int h = 0; h < 2; ++h) {
                const size_t idx = (size_t)(r0 + h * 8) * N + cn;
                if (Cf) *(float2*)(Cf + idx) = make_float2(v[h][0], v[h][1]);
                if (Chi) {
                    __nv_bfloat16 h0 = __float2bfloat16(v[h][0]);
                    __nv_bfloat16 h1 = __float2bfloat16(v[h][1]);
                    __nv_bfloat16 l0 = __float2bfloat16(v[h][0] - __bfloat162float(h0));
                    __nv_bfloat16 l1 = __float2bfloat16(v[h][1] - __bfloat162float(h1));
                    *(uint32_t*)(Chi + idx) = pk_bf16(h0, h1);
                    *(uint32_t*)(Clo + idx) = pk_bf16(l0, l1);
                }
            }
        }
    }
}

// ---------------------------------------------------------------------------
// y_hat[r] = dot(feat_l[r,:], W3) + b3   (one warp per row)
// ---------------------------------------------------------------------------
__global__ void yhat_kernel(const float* __restrict__ feat_l,
                            const float* __restrict__ W3,
                            const float* __restrict__ b3,
                            float* __restrict__ out) {
    int warp = (blockIdx.x * blockDim.x + threadIdx.x) >> 5;
    int lane = threadIdx.x & 31;
    if (warp >= SL) return;
    const float* row = feat_l + (size_t)warp * H2;
    float s = 0.0f;
#pragma unroll
    for (int d = lane; d < H2; d += 32) s += row[d] * W3[d];
#pragma unroll
    for (int off = 16; off > 0; off >>= 1)
        s += __shfl_down_sync(0xFFFFFFFFu, s, off);
    if (lane == 0) out[warp] = s + b3[0];
}

// ---------------------------------------------------------------------------
// JAX threefry2x32 (20 rounds)
// ---------------------------------------------------------------------------
__device__ __forceinline__ uint32_t rotl32(uint32_t v, int d) {
    return (v << d) | (v >> (32 - d));
}
__device__ __forceinline__ void threefry2x32(uint32_t k0, uint32_t k1,
                                             uint32_t x0, uint32_t x1,
                                             uint32_t& o0, uint32_t& o1) {
    uint32_t k2 = k0 ^ k1 ^ 0x1BD11BDAu;
    x0 += k0; x1 += k1;
#define TF_RND(r) { x0 += x1; x1 = rotl32(x1, r); x1 ^= x0; }
    TF_RND(13) TF_RND(15) TF_RND(26) TF_RND(6)
    x0 += k1; x1 += k2 + 1u;
    TF_RND(17) TF_RND(29) TF_RND(16) TF_RND(24)
    x0 += k2; x1 += k0 + 2u;
    TF_RND(13) TF_RND(15) TF_RND(26) TF_RND(6)
    x0 += k0; x1 += k1 + 3u;
    TF_RND(17) TF_RND(29) TF_RND(16) TF_RND(24)
    x0 += k1; x1 += k2 + 4u;
    TF_RND(13) TF_RND(15) TF_RND(26) TF_RND(6)
    x0 += k2; x1 += k0 + 5u;
#undef TF_RND
    o0 = x0; o1 = x1;
}

// ---------------------------------------------------------------------------
// Pair sampling — JAX partitionable threefry (verified PASS in R9/R11):
//   split(key)[j] = TF(key, (0,j)); bits[i] = o0^o1 of TF(key,(0,i));
//   randint pow2 span -> bits(split(key)[1]) & (span-1)
// ---------------------------------------------------------------------------
__global__ void sample_pairs_kernel(const float* __restrict__ y_l,
                                    int* __restrict__ a_out,
                                    int* __restrict__ b_out) {
    int s = blockIdx.x * blockDim.x + threadIdx.x;
    if (s >= SU) return;

    uint32_t o0, o1;
    uint32_t ka0, ka1, kb0, kb1;
    threefry2x32(0u, 42u, 0u, 0u, ka0, ka1);
    threefry2x32(0u, 42u, 0u, 1u, kb0, kb1);

    uint32_t ka2_0, ka2_1, kb2_0, kb2_1;
    threefry2x32(ka0, ka1, 0u, 1u, ka2_0, ka2_1);
    threefry2x32(kb0, kb1, 0u, 1u, kb2_0, kb2_1);

    int a = -1, b = -1, a_first = 0, b_first = 0;
#pragma unroll
    for (int k = 0; k < K_TRIES; k++) {
        uint32_t i = (uint32_t)s * K_TRIES + k;
        threefry2x32(ka2_0, ka2_1, 0u, i, o0, o1);
        int ia = (int)((o0 ^ o1) & (SL - 1));
        threefry2x32(kb2_0, kb2_1, 0u, i, o0, o1);
        int ib = (int)((o0 ^ o1) & (SL - 1));
        if (k == 0) { a_first = ia; b_first = ib; }
        if (a < 0 && ia != ib && y_l[ia] != y_l[ib]) { a = ia; b = ib; }
    }
    if (a < 0) { a = a_first; b = b_first; }
    a_out[s] = a;
    b_out[s] = b;
}

// ---------------------------------------------------------------------------
// feat_comb[s] = k * feat_l[a] + (1-k) * feat_l[b]
// ---------------------------------------------------------------------------
__global__ void combine_kernel(const float* __restrict__ feat_l,
                               const float* __restrict__ y_l,
                               const float* __restrict__ y_u,
                               const int* __restrict__ a_idx,
                               const int* __restrict__ b_idx,
                               float* __restrict__ out) {
    int s = blockIdx.x;
    int a = a_idx[s], b = b_idx[s];
    float ya = y_l[a], yb = y_l[b];
    float kc = (y_u[s] - yb) / (ya - yb);
    float km = 1.0f - kc;
    const float4* fa = (const float4*)(feat_l + (size_t)a * H2);
    const float4* fb = (const float4*)(feat_l + (size_t)b * H2);
    float4* o = (float4*)(out + (size_t)s * H2);
    for (int d = threadIdx.x; d < H2 / 4; d += blockDim.x) {
        float4 va = fa[d], vb = fb[d], r;
        r.x = kc * va.x + km * vb.x;
        r.y = kc * va.y + km * vb.y;
        r.z = kc * va.z + km * vb.z;
        r.w = kc * va.w + km * vb.w;
        o[d] = r;
    }
}

// ---------------------------------------------------------------------------
// Launch
// ---------------------------------------------------------------------------
extern "C" void kernel_launch(void* const* d_in, const int* in_sizes, int n_in,
                              void* d_out, int out_size) {
    const float* X_l = (const float*)d_in[0];
    const float* y_l = (const float*)d_in[1];
    const float* X_u = (const float*)d_in[2];
    const float* y_u = (const float*)d_in[3];
    const float* W1  = (const float*)d_in[4];
    const float* b1  = (const float*)d_in[5];
    const float* W2  = (const float*)d_in[6];
    const float* b2  = (const float*)d_in[7];
    const float* W3  = (const float*)d_in[8];
    const float* b3  = (const float*)d_in[9];

    float* out = (float*)d_out;
    float* out_feat_u    = out;                       // [SU, H2]
    float* out_feat_comb = out + (size_t)SU * H2;     // [SU, H2]
    float* out_yhat      = out + (size_t)2 * SU * H2; // [SL, 1]

    __nv_bfloat16 *pXuh, *pXul, *pXlh, *pXll, *pW1h, *pW1l, *pW2h, *pW2l, *pHh, *pHl;
    float* pfl;
    int *pa, *pb;
    cudaGetSymbolAddress((void**)&pXuh, g_Xu_hi);
    cudaGetSymbolAddress((void**)&pXul, g_Xu_lo);
    cudaGetSymbolAddress((void**)&pXlh, g_Xl_hi);
    cudaGetSymbolAddress((void**)&pXll, g_Xl_lo);
    cudaGetSymbolAddress((void**)&pW1h, g_W1_hi);
    cudaGetSymbolAddress((void**)&pW1l, g_W1_lo);
    cudaGetSymbolAddress((void**)&pW2h, g_W2_hi);
    cudaGetSymbolAddress((void**)&pW2l, g_W2_lo);
    cudaGetSymbolAddress((void**)&pHh,  g_h_hi);
    cudaGetSymbolAddress((void**)&pHl,  g_h_lo);
    cudaGetSymbolAddress((void**)&pfl,  g_feat_l);
    cudaGetSymbolAddress((void**)&pa,   g_a);
    cudaGetSymbolAddress((void**)&pb,   g_b);

    cudaFuncSetAttribute(gemm_bf16x3,
                         cudaFuncAttributeMaxDynamicSharedMemorySize, 2 * ST_SZ);

    // --- one-time fp32 -> bf16 hi/lo splits
    auto cvt = [&](const float* src, __nv_bfloat16* hi, __nv_bfloat16* lo, size_t n) {
        int n4 = (int)(n / 4);
        cvt_hilo<<<(n4 + 255) / 256, 256>>>((const float4*)src, (uint2*)hi, (uint2*)lo, n4);
    };
    cvt(X_u, pXuh, pXul, (size_t)SU * DIM_X);
    cvt(X_l, pXlh, pXll, (size_t)SL * DIM_X);
    cvt(W1,  pW1h, pW1l, (size_t)DIM_X * H1);
    cvt(W2,  pW2h, pW2l, (size_t)H1 * H2);

    // --- unlabeled branch
    gemm_bf16x3<<<dim3(H1 / BN, SU / BM), 256, 2 * ST_SZ>>>(
        pXuh, pXul, pW1h, pW1l, b1, nullptr, pHh, pHl, SU, H1, DIM_X);
    gemm_bf16x3<<<dim3(H2 / BN, SU / BM), 256, 2 * ST_SZ>>>(
        pHh, pHl, pW2h, pW2l, b2, out_feat_u, nullptr, nullptr, SU, H2, H1);

    // --- labeled branch (reuses g_h after GEMM2u has consumed it)
    gemm_bf16x3<<<dim3(H1 / BN, SL / BM), 256, 2 * ST_SZ>>>(
        pXlh, pXll, pW1h, pW1l, b1, nullptr, pHh, pHl, SL, H1, DIM_X);
    gemm_bf16x3<<<dim3(H2 / BN, SL / BM), 256, 2 * ST_SZ>>>(
        pHh, pHl, pW2h, pW2l, b2, pfl, nullptr, nullptr, SL, H2, H1);

    // --- y_hat
    yhat_kernel<<<SL / 8, 256>>>(pfl, W3, b3, out_yhat);

    // --- pair sampling + combine
    sample_pairs_kernel<<<SU / 256, 256>>>(y_l, pa, pb);
    combine_kernel<<<SU, 128>>>(pfl, y_l, y_u, pa, pb, out_feat_comb);
}